// round 1
// baseline (speedup 1.0000x reference)
#include <cuda_runtime.h>
#include <math.h>

#define NNODES 100000
#define DIN 256
#define DOUT 64
#define NEDGE 3200000

// ---------------- scratch (device globals; no allocation allowed) ----------------
__device__ float g_self_p[NNODES * DOUT];   // x_p @ w_self_p
__device__ float g_rels_p[NNODES * DOUT];   // x_p @ w_rel_a_p   (source feats for out_a's aggregation)
__device__ float g_self_a[NNODES * DOUT];   // x_a @ w_self_a
__device__ float g_rels_a[NNODES * DOUT];   // x_a @ w_rel_p_a   (source feats for out_p's aggregation)
__device__ float g_nb_p[NNODES * DOUT];
__device__ float g_nb_a[NNODES * DOUT];
__device__ float g_vkq[4 * DOUT];           // [vk_p | vq_p | vk_a | vq_a]

// ---------------- tiny: fold attention projections into 64-vectors ----------------
// vk[d] = sum_a w_keys[d][a] * w_att[a];  vq[d] = sum_a w_query[d][a] * w_att[64+a]
__global__ void vkq_kernel(const float* __restrict__ wk_p, const float* __restrict__ wq_p,
                           const float* __restrict__ wa_p,
                           const float* __restrict__ wk_a, const float* __restrict__ wq_a,
                           const float* __restrict__ wa_a) {
    int t = threadIdx.x;           // 256 threads
    if (t >= 4 * DOUT) return;
    int which = t >> 6, d = t & 63;
    const float* W; const float* a;
    if (which == 0)      { W = wk_p; a = wa_p; }
    else if (which == 1) { W = wq_p; a = wa_p + DOUT; }
    else if (which == 2) { W = wk_a; a = wa_a; }
    else                 { W = wq_a; a = wa_a + DOUT; }
    float s = 0.f;
#pragma unroll 16
    for (int i = 0; i < DOUT; i++) s += W[d * DOUT + i] * a[i];
    g_vkq[which * DOUT + d] = s;
}

// ---------------- zero the aggregation buffers ----------------
__global__ void zero_kernel() {
    int i = blockIdx.x * blockDim.x + threadIdx.x;
    const int n4 = NNODES * DOUT / 4;
    if (i < n4) {
        ((float4*)g_nb_p)[i] = make_float4(0.f, 0.f, 0.f, 0.f);
        ((float4*)g_nb_a)[i] = make_float4(0.f, 0.f, 0.f, 0.f);
    }
}

// ---------------- fused dual-weight GEMM: C[:, :64]=X@Ws, C[:, 64:]=X@Wr ----------------
// BM=64 rows, BN=128 cols (Ws|Wr), BK=16, 128 threads, 8x8 micro-tile per thread.
#define BM 64
#define BN 128
#define BK 16

__global__ __launch_bounds__(128) void gemm_dual_kernel(
    const float* __restrict__ X, const float* __restrict__ Ws, const float* __restrict__ Wr,
    float* __restrict__ Cs, float* __restrict__ Cr, int nrows)
{
    __shared__ float As[BK][BM];        // transposed tile: As[k][m]
    __shared__ float Bs[BK][BN];

    const int tid = threadIdx.x;        // 0..127
    const int block_row = blockIdx.x * BM;
    const int rg = tid >> 4;            // 0..7  (row group of 8)
    const int cg = tid & 15;            // 0..15 (col group of 8)

    float acc[8][8];
#pragma unroll
    for (int i = 0; i < 8; i++)
#pragma unroll
        for (int j = 0; j < 8; j++) acc[i][j] = 0.f;

    for (int k0 = 0; k0 < DIN; k0 += BK) {
        // Load A tile (64 rows x 16 k) as float4, transpose into As[k][m].
        // 64*16/4 = 256 float4 loads, 2 per thread.
#pragma unroll
        for (int i = tid; i < BM * BK / 4; i += 128) {
            int m = i >> 2, kq = i & 3;
            int r = block_row + m;
            float4 v = make_float4(0.f, 0.f, 0.f, 0.f);
            if (r < nrows)
                v = *(const float4*)(X + (size_t)r * DIN + k0 + kq * 4);
            As[kq * 4 + 0][m] = v.x;
            As[kq * 4 + 1][m] = v.y;
            As[kq * 4 + 2][m] = v.z;
            As[kq * 4 + 3][m] = v.w;
        }
        // Load B tile: 16 k-rows x 128 cols (first 64 from Ws, next 64 from Wr).
        // 16*128/4 = 512 float4, 4 per thread.
#pragma unroll
        for (int i = tid; i < BK * BN / 4; i += 128) {
            int k = i >> 5;             // 0..15
            int c4 = i & 31;            // 0..31 quads
            float4 v;
            if (c4 < 16) v = *(const float4*)(Ws + (size_t)(k0 + k) * DOUT + c4 * 4);
            else         v = *(const float4*)(Wr + (size_t)(k0 + k) * DOUT + (c4 - 16) * 4);
            *(float4*)&Bs[k][c4 * 4] = v;
        }
        __syncthreads();

#pragma unroll
        for (int k = 0; k < BK; k++) {
            float4 a0 = *(const float4*)&As[k][rg * 8];
            float4 a1 = *(const float4*)&As[k][rg * 8 + 4];
            float4 b0 = *(const float4*)&Bs[k][cg * 8];
            float4 b1 = *(const float4*)&Bs[k][cg * 8 + 4];
            float a[8] = {a0.x, a0.y, a0.z, a0.w, a1.x, a1.y, a1.z, a1.w};
            float b[8] = {b0.x, b0.y, b0.z, b0.w, b1.x, b1.y, b1.z, b1.w};
#pragma unroll
            for (int i = 0; i < 8; i++)
#pragma unroll
                for (int j = 0; j < 8; j++)
                    acc[i][j] = fmaf(a[i], b[j], acc[i][j]);
        }
        __syncthreads();
    }

    // Store: each thread's 8 cols live entirely in Cs (cg<8) or Cr (cg>=8).
    const int cbase = cg * 8;
    float* Cout = (cbase < 64) ? Cs : Cr;
    const int ccol = (cbase < 64) ? cbase : (cbase - 64);
#pragma unroll
    for (int i = 0; i < 8; i++) {
        int r = block_row + rg * 8 + i;
        if (r < nrows) {
            *(float4*)(Cout + (size_t)r * DOUT + ccol) =
                make_float4(acc[i][0], acc[i][1], acc[i][2], acc[i][3]);
            *(float4*)(Cout + (size_t)r * DOUT + ccol + 4) =
                make_float4(acc[i][4], acc[i][5], acc[i][6], acc[i][7]);
        }
    }
}

// ---------------- edge-parallel SpMM: dst[row] += val * src[col], 16 threads/edge ----------------
__global__ __launch_bounds__(256) void spmm_kernel(
    const int* __restrict__ row, const int* __restrict__ col, const float* __restrict__ val,
    const float* __restrict__ src, float* __restrict__ dst)
{
    long long idx = (long long)blockIdx.x * blockDim.x + threadIdx.x;
    int e = (int)(idx >> 4);
    int c = (int)(idx & 15);
    if (e >= NEDGE) return;
    int r = __ldg(row + e);
    int s = __ldg(col + e);
    float v = __ldg(val + e);
    const float4 x = *(const float4*)(src + (size_t)s * DOUT + c * 4);
    float4 y = make_float4(v * x.x, v * x.y, v * x.z, v * x.w);
    float* p = dst + (size_t)r * DOUT + c * 4;
    asm volatile("red.global.add.v4.f32 [%0], {%1,%2,%3,%4};"
                 :: "l"(p), "f"(y.x), "f"(y.y), "f"(y.z), "f"(y.w) : "memory");
}

// ---------------- attention mix + output, warp per node ----------------
__global__ __launch_bounds__(256) void finalize_kernel(
    const float* __restrict__ selfft, const float* __restrict__ nbft,
    const float* __restrict__ bias, const float* __restrict__ vk, const float* __restrict__ vq,
    float* __restrict__ out, float* __restrict__ att)
{
    int gw = (blockIdx.x * blockDim.x + threadIdx.x) >> 5;
    int lane = threadIdx.x & 31;
    if (gw >= NNODES) return;
    size_t base = (size_t)gw * DOUT;

    float s0 = selfft[base + lane],      s1 = selfft[base + 32 + lane];
    float n0 = nbft[base + lane],        n1 = nbft[base + 32 + lane];
    float vk0 = vk[lane], vk1 = vk[32 + lane];
    float vq0 = vq[lane], vq1 = vq[32 + lane];

    float d_skq = s0 * (vk0 + vq0) + s1 * (vk1 + vq1);   // self·(vk+vq)
    float d_sq  = s0 * vq0 + s1 * vq1;                   // self·vq
    float d_nk  = n0 * vk0 + n1 * vk1;                   // nb·vk
#pragma unroll
    for (int o = 16; o; o >>= 1) {
        d_skq += __shfl_xor_sync(0xffffffffu, d_skq, o);
        d_sq  += __shfl_xor_sync(0xffffffffu, d_sq,  o);
        d_nk  += __shfl_xor_sync(0xffffffffu, d_nk,  o);
    }
    float e0 = d_skq;
    float e1 = d_nk + d_sq;
    e0 = (e0 > 0.f) ? e0 : expm1f(e0);   // elu
    e1 = (e1 > 0.f) ? e1 : expm1f(e1);
    float m = fmaxf(e0, e1);
    float a0 = expf(e0 - m), a1 = expf(e1 - m);
    float inv = 1.f / (a0 + a1);
    a0 *= inv; a1 *= inv;

    out[base + lane]      = fmaf(a0, s0, fmaf(a1, n0, bias[lane]));
    out[base + 32 + lane] = fmaf(a0, s1, fmaf(a1, n1, bias[32 + lane]));
    if (lane == 0) { att[(size_t)gw * 2] = a0; att[(size_t)gw * 2 + 1] = a1; }
}

// ---------------- launch ----------------
extern "C" void kernel_launch(void* const* d_in, const int* in_sizes, int n_in,
                              void* d_out, int out_size) {
    const float* x_p       = (const float*)d_in[0];
    const float* x_a       = (const float*)d_in[1];
    const int*   adj_a_row = (const int*)d_in[2];
    const int*   adj_a_col = (const int*)d_in[3];
    const float* adj_a_val = (const float*)d_in[4];
    const int*   adj_p_row = (const int*)d_in[5];
    const int*   adj_p_col = (const int*)d_in[6];
    const float* adj_p_val = (const float*)d_in[7];
    const float* w_self_p  = (const float*)d_in[8];
    const float* w_rel_p_a = (const float*)d_in[9];
    const float* bias_p    = (const float*)d_in[10];
    const float* w_query_p = (const float*)d_in[11];
    const float* w_keys_p  = (const float*)d_in[12];
    const float* w_att_p   = (const float*)d_in[13];
    const float* w_self_a  = (const float*)d_in[14];
    const float* w_rel_a_p = (const float*)d_in[15];
    const float* bias_a    = (const float*)d_in[16];
    const float* w_query_a = (const float*)d_in[17];
    const float* w_keys_a  = (const float*)d_in[18];
    const float* w_att_a   = (const float*)d_in[19];

    float* out = (float*)d_out;
    float* out_p = out;
    float* out_a = out + (size_t)NNODES * DOUT;
    float* att_p = out + (size_t)2 * NNODES * DOUT;
    float* att_a = att_p + (size_t)NNODES * 2;

    // resolve device-global scratch addresses (host-side symbol lookups; no allocation)
    float *p_self_p, *p_rels_p, *p_self_a, *p_rels_a, *p_nb_p, *p_nb_a, *p_vkq;
    cudaGetSymbolAddress((void**)&p_self_p, g_self_p);
    cudaGetSymbolAddress((void**)&p_rels_p, g_rels_p);
    cudaGetSymbolAddress((void**)&p_self_a, g_self_a);
    cudaGetSymbolAddress((void**)&p_rels_a, g_rels_a);
    cudaGetSymbolAddress((void**)&p_nb_p, g_nb_p);
    cudaGetSymbolAddress((void**)&p_nb_a, g_nb_a);
    cudaGetSymbolAddress((void**)&p_vkq, g_vkq);

    // 1. fold attention projections
    vkq_kernel<<<1, 256>>>(w_keys_p, w_query_p, w_att_p, w_keys_a, w_query_a, w_att_a);

    // 2. zero aggregation buffers
    zero_kernel<<<(NNODES * DOUT / 4 + 255) / 256, 256>>>();

    // 3. fused dual GEMMs (each X read once, two weight matrices)
    int gblocks = (NNODES + BM - 1) / BM;
    gemm_dual_kernel<<<gblocks, 128>>>(x_p, w_self_p, w_rel_a_p, p_self_p, p_rels_p, NNODES);
    gemm_dual_kernel<<<gblocks, 128>>>(x_a, w_self_a, w_rel_p_a, p_self_a, p_rels_a, NNODES);

    // 4. SpMM aggregations
    long long sthreads = (long long)NEDGE * 16;
    int sblocks = (int)((sthreads + 255) / 256);
    // out_p's neighbor agg: adj_a over (x_a @ w_rel_p_a) = g_rels_a
    spmm_kernel<<<sblocks, 256>>>(adj_a_row, adj_a_col, adj_a_val, p_rels_a, p_nb_p);
    // out_a's neighbor agg: adj_p over (x_p @ w_rel_a_p) = g_rels_p
    spmm_kernel<<<sblocks, 256>>>(adj_p_row, adj_p_col, adj_p_val, p_rels_p, p_nb_a);

    // 5. attention + output
    int fblocks = (NNODES * 32 + 255) / 256;
    finalize_kernel<<<fblocks, 256>>>(p_self_p, p_nb_p, bias_p, p_vkq + 0 * DOUT, p_vkq + 1 * DOUT,
                                      out_p, att_p);
    finalize_kernel<<<fblocks, 256>>>(p_self_a, p_nb_a, bias_a, p_vkq + 2 * DOUT, p_vkq + 3 * DOUT,
                                      out_a, att_a);
}

// round 2
// speedup vs baseline: 1.1706x; 1.1706x over previous
#include <cuda_runtime.h>
#include <math.h>

#define NNODES 100000
#define DIN 256
#define DOUT 64
#define NEDGE 3200000
#define SCAN_BLK 1024
#define NB ((NNODES + SCAN_BLK - 1) / SCAN_BLK)   // 98

// ---------------- scratch (device globals; no allocation allowed) ----------------
__device__ float g_self_p[NNODES * DOUT];   // x_p @ w_self_p
__device__ float g_rels_p[NNODES * DOUT];   // x_p @ w_rel_a_p
__device__ float g_self_a[NNODES * DOUT];   // x_a @ w_self_a
__device__ float g_rels_a[NNODES * DOUT];   // x_a @ w_rel_p_a
__device__ float g_nb_p[NNODES * DOUT];
__device__ float g_nb_a[NNODES * DOUT];
__device__ float g_vkq[4 * DOUT];

// CSR build scratch (2 relations)
__device__ int  g_cnt[2][NNODES];
__device__ int  g_off[2][NNODES];
__device__ int  g_cur[2][NNODES];
__device__ int  g_bsum[2][NB + 1];
__device__ int2 g_edge[2][NEDGE];           // packed {col, val-bits}

// ---------------- fold attention projections into 64-vectors ----------------
__global__ void vkq_kernel(const float* __restrict__ wk_p, const float* __restrict__ wq_p,
                           const float* __restrict__ wa_p,
                           const float* __restrict__ wk_a, const float* __restrict__ wq_a,
                           const float* __restrict__ wa_a) {
    int t = threadIdx.x;
    if (t >= 4 * DOUT) return;
    int which = t >> 6, d = t & 63;
    const float* W; const float* a;
    if (which == 0)      { W = wk_p; a = wa_p; }
    else if (which == 1) { W = wq_p; a = wa_p + DOUT; }
    else if (which == 2) { W = wk_a; a = wa_a; }
    else                 { W = wq_a; a = wa_a + DOUT; }
    float s = 0.f;
#pragma unroll 16
    for (int i = 0; i < DOUT; i++) s += W[d * DOUT + i] * a[i];
    g_vkq[which * DOUT + d] = s;
}

// ---------------- CSR build ----------------
__global__ void zero_cnt_kernel() {
    int i = blockIdx.x * blockDim.x + threadIdx.x;
    if (i < 2 * NNODES) ((int*)g_cnt)[i] = 0;
}

__global__ void hist_kernel(const int* __restrict__ row, int* __restrict__ cnt) {
    int e = blockIdx.x * blockDim.x + threadIdx.x;
    if (e < NEDGE) atomicAdd(cnt + __ldg(row + e), 1);   // no return use -> RED
}

__global__ void scan1_kernel(const int* __restrict__ cnt, int* __restrict__ off,
                             int* __restrict__ bsum) {
    __shared__ int s[SCAN_BLK];
    int t = threadIdx.x;
    int i = blockIdx.x * SCAN_BLK + t;
    int v = (i < NNODES) ? cnt[i] : 0;
    s[t] = v;
    __syncthreads();
#pragma unroll
    for (int o = 1; o < SCAN_BLK; o <<= 1) {
        int x = (t >= o) ? s[t - o] : 0;
        __syncthreads();
        s[t] += x;
        __syncthreads();
    }
    if (i < NNODES) off[i] = s[t] - v;      // exclusive
    if (t == SCAN_BLK - 1) bsum[blockIdx.x] = s[t];
}

__global__ void scan2_kernel(int* __restrict__ bsum) {
    if (threadIdx.x == 0) {
        int acc = 0;
        for (int b = 0; b < NB; b++) { int x = bsum[b]; bsum[b] = acc; acc += x; }
    }
}

__global__ void scan3_kernel(int* __restrict__ off, int* __restrict__ cur,
                             const int* __restrict__ bsum) {
    int i = blockIdx.x * blockDim.x + threadIdx.x;
    if (i < NNODES) {
        int o = off[i] + bsum[i >> 10];
        off[i] = o;
        cur[i] = o;
    }
}

__global__ void scatter_kernel(const int* __restrict__ row, const int* __restrict__ col,
                               const float* __restrict__ val, int* __restrict__ cur,
                               int2* __restrict__ edges) {
    int e = blockIdx.x * blockDim.x + threadIdx.x;
    if (e >= NEDGE) return;
    int r = __ldg(row + e);
    int pos = atomicAdd(cur + r, 1);
    edges[pos] = make_int2(__ldg(col + e), __float_as_int(__ldg(val + e)));
}

// ---------------- gather-only SpMM: warp per dst node ----------------
__global__ __launch_bounds__(256) void spmm_csr_kernel(
    const int* __restrict__ off, const int* __restrict__ cnt, const int2* __restrict__ edges,
    const float* __restrict__ src, float* __restrict__ dst)
{
    int gw = (blockIdx.x * blockDim.x + threadIdx.x) >> 5;
    int lane = threadIdx.x & 31;
    if (gw >= NNODES) return;
    int start = __ldg(off + gw);
    int deg   = __ldg(cnt + gw);

    float acc0 = 0.f, acc1 = 0.f;
    int i = 0;
    for (; i + 2 <= deg; i += 2) {                  // 2-deep pipeline for MLP
        int2 e0 = __ldg(edges + start + i);
        int2 e1 = __ldg(edges + start + i + 1);
        const float* s0 = src + (size_t)e0.x * DOUT;
        const float* s1 = src + (size_t)e1.x * DOUT;
        float v0 = __int_as_float(e0.y), v1 = __int_as_float(e1.y);
        float x00 = __ldg(s0 + lane), x01 = __ldg(s0 + 32 + lane);
        float x10 = __ldg(s1 + lane), x11 = __ldg(s1 + 32 + lane);
        acc0 = fmaf(v0, x00, acc0); acc1 = fmaf(v0, x01, acc1);
        acc0 = fmaf(v1, x10, acc0); acc1 = fmaf(v1, x11, acc1);
    }
    if (i < deg) {
        int2 e0 = __ldg(edges + start + i);
        const float* s0 = src + (size_t)e0.x * DOUT;
        float v0 = __int_as_float(e0.y);
        acc0 = fmaf(v0, __ldg(s0 + lane), acc0);
        acc1 = fmaf(v0, __ldg(s0 + 32 + lane), acc1);
    }
    dst[(size_t)gw * DOUT + lane] = acc0;
    dst[(size_t)gw * DOUT + 32 + lane] = acc1;
}

// ---------------- fused dual-weight GEMM with packed f32x2 FMA ----------------
#define BM 64
#define BN 128
#define BK 16

union F2 { float2 f; unsigned long long u; };

__global__ __launch_bounds__(128) void gemm_dual_kernel(
    const float* __restrict__ X, const float* __restrict__ Ws, const float* __restrict__ Wr,
    float* __restrict__ Cs, float* __restrict__ Cr, int nrows)
{
    __shared__ float As[BK][BM];        // transposed tile: As[k][m]
    __shared__ float Bs[BK][BN];

    const int tid = threadIdx.x;        // 0..127
    const int block_row = blockIdx.x * BM;
    const int rg = tid >> 4;            // 0..7  (row group of 8)
    const int cg = tid & 15;            // 0..15 (col group of 8)

    // acc[ip][j]: rows (2ip, 2ip+1) of this thread's 8-row strip, col j
    F2 acc[4][8];
#pragma unroll
    for (int i = 0; i < 4; i++)
#pragma unroll
        for (int j = 0; j < 8; j++) acc[i][j].u = 0ULL;

    for (int k0 = 0; k0 < DIN; k0 += BK) {
#pragma unroll
        for (int i = tid; i < BM * BK / 4; i += 128) {
            int m = i >> 2, kq = i & 3;
            int r = block_row + m;
            float4 v = make_float4(0.f, 0.f, 0.f, 0.f);
            if (r < nrows)
                v = *(const float4*)(X + (size_t)r * DIN + k0 + kq * 4);
            As[kq * 4 + 0][m] = v.x;
            As[kq * 4 + 1][m] = v.y;
            As[kq * 4 + 2][m] = v.z;
            As[kq * 4 + 3][m] = v.w;
        }
#pragma unroll
        for (int i = tid; i < BK * BN / 4; i += 128) {
            int k = i >> 5;
            int c4 = i & 31;
            float4 v;
            if (c4 < 16) v = *(const float4*)(Ws + (size_t)(k0 + k) * DOUT + c4 * 4);
            else         v = *(const float4*)(Wr + (size_t)(k0 + k) * DOUT + (c4 - 16) * 4);
            *(float4*)&Bs[k][c4 * 4] = v;
        }
        __syncthreads();

#pragma unroll
        for (int k = 0; k < BK; k++) {
            float4 a0 = *(const float4*)&As[k][rg * 8];
            float4 a1 = *(const float4*)&As[k][rg * 8 + 4];
            float4 b0 = *(const float4*)&Bs[k][cg * 8];
            float4 b1 = *(const float4*)&Bs[k][cg * 8 + 4];

            F2 ap[4];
            ap[0].f = make_float2(a0.x, a0.y);
            ap[1].f = make_float2(a0.z, a0.w);
            ap[2].f = make_float2(a1.x, a1.y);
            ap[3].f = make_float2(a1.z, a1.w);

            float bv[8] = {b0.x, b0.y, b0.z, b0.w, b1.x, b1.y, b1.z, b1.w};
#pragma unroll
            for (int j = 0; j < 8; j++) {
                F2 bd; bd.f = make_float2(bv[j], bv[j]);
#pragma unroll
                for (int ip = 0; ip < 4; ip++) {
                    asm("fma.rn.f32x2 %0, %1, %2, %3;"
                        : "=l"(acc[ip][j].u)
                        : "l"(ap[ip].u), "l"(bd.u), "l"(acc[ip][j].u));
                }
            }
        }
        __syncthreads();
    }

    const int cbase = cg * 8;
    float* Cout = (cbase < 64) ? Cs : Cr;
    const int ccol = (cbase < 64) ? cbase : (cbase - 64);
#pragma unroll
    for (int ip = 0; ip < 4; ip++) {
        int r0 = block_row + rg * 8 + 2 * ip;
        int r1 = r0 + 1;
        if (r0 < nrows) {
            *(float4*)(Cout + (size_t)r0 * DOUT + ccol) =
                make_float4(acc[ip][0].f.x, acc[ip][1].f.x, acc[ip][2].f.x, acc[ip][3].f.x);
            *(float4*)(Cout + (size_t)r0 * DOUT + ccol + 4) =
                make_float4(acc[ip][4].f.x, acc[ip][5].f.x, acc[ip][6].f.x, acc[ip][7].f.x);
        }
        if (r1 < nrows) {
            *(float4*)(Cout + (size_t)r1 * DOUT + ccol) =
                make_float4(acc[ip][0].f.y, acc[ip][1].f.y, acc[ip][2].f.y, acc[ip][3].f.y);
            *(float4*)(Cout + (size_t)r1 * DOUT + ccol + 4) =
                make_float4(acc[ip][4].f.y, acc[ip][5].f.y, acc[ip][6].f.y, acc[ip][7].f.y);
        }
    }
}

// ---------------- attention mix + output, warp per node ----------------
__global__ __launch_bounds__(256) void finalize_kernel(
    const float* __restrict__ selfft, const float* __restrict__ nbft,
    const float* __restrict__ bias, const float* __restrict__ vk, const float* __restrict__ vq,
    float* __restrict__ out, float* __restrict__ att)
{
    int gw = (blockIdx.x * blockDim.x + threadIdx.x) >> 5;
    int lane = threadIdx.x & 31;
    if (gw >= NNODES) return;
    size_t base = (size_t)gw * DOUT;

    float s0 = selfft[base + lane],      s1 = selfft[base + 32 + lane];
    float n0 = nbft[base + lane],        n1 = nbft[base + 32 + lane];
    float vk0 = vk[lane], vk1 = vk[32 + lane];
    float vq0 = vq[lane], vq1 = vq[32 + lane];

    float d_skq = s0 * (vk0 + vq0) + s1 * (vk1 + vq1);
    float d_sq  = s0 * vq0 + s1 * vq1;
    float d_nk  = n0 * vk0 + n1 * vk1;
#pragma unroll
    for (int o = 16; o; o >>= 1) {
        d_skq += __shfl_xor_sync(0xffffffffu, d_skq, o);
        d_sq  += __shfl_xor_sync(0xffffffffu, d_sq,  o);
        d_nk  += __shfl_xor_sync(0xffffffffu, d_nk,  o);
    }
    float e0 = d_skq;
    float e1 = d_nk + d_sq;
    e0 = (e0 > 0.f) ? e0 : expm1f(e0);
    e1 = (e1 > 0.f) ? e1 : expm1f(e1);
    float m = fmaxf(e0, e1);
    float a0 = expf(e0 - m), a1 = expf(e1 - m);
    float inv = 1.f / (a0 + a1);
    a0 *= inv; a1 *= inv;

    out[base + lane]      = fmaf(a0, s0, fmaf(a1, n0, bias[lane]));
    out[base + 32 + lane] = fmaf(a0, s1, fmaf(a1, n1, bias[32 + lane]));
    if (lane == 0) { att[(size_t)gw * 2] = a0; att[(size_t)gw * 2 + 1] = a1; }
}

// ---------------- launch ----------------
extern "C" void kernel_launch(void* const* d_in, const int* in_sizes, int n_in,
                              void* d_out, int out_size) {
    const float* x_p       = (const float*)d_in[0];
    const float* x_a       = (const float*)d_in[1];
    const int*   adj_a_row = (const int*)d_in[2];
    const int*   adj_a_col = (const int*)d_in[3];
    const float* adj_a_val = (const float*)d_in[4];
    const int*   adj_p_row = (const int*)d_in[5];
    const int*   adj_p_col = (const int*)d_in[6];
    const float* adj_p_val = (const float*)d_in[7];
    const float* w_self_p  = (const float*)d_in[8];
    const float* w_rel_p_a = (const float*)d_in[9];
    const float* bias_p    = (const float*)d_in[10];
    const float* w_query_p = (const float*)d_in[11];
    const float* w_keys_p  = (const float*)d_in[12];
    const float* w_att_p   = (const float*)d_in[13];
    const float* w_self_a  = (const float*)d_in[14];
    const float* w_rel_a_p = (const float*)d_in[15];
    const float* bias_a    = (const float*)d_in[16];
    const float* w_query_a = (const float*)d_in[17];
    const float* w_keys_a  = (const float*)d_in[18];
    const float* w_att_a   = (const float*)d_in[19];

    float* out = (float*)d_out;
    float* out_p = out;
    float* out_a = out + (size_t)NNODES * DOUT;
    float* att_p = out + (size_t)2 * NNODES * DOUT;
    float* att_a = att_p + (size_t)NNODES * 2;

    float *p_self_p, *p_rels_p, *p_self_a, *p_rels_a, *p_nb_p, *p_nb_a, *p_vkq;
    int *p_cnt, *p_off, *p_cur, *p_bsum;
    int2 *p_edge;
    cudaGetSymbolAddress((void**)&p_self_p, g_self_p);
    cudaGetSymbolAddress((void**)&p_rels_p, g_rels_p);
    cudaGetSymbolAddress((void**)&p_self_a, g_self_a);
    cudaGetSymbolAddress((void**)&p_rels_a, g_rels_a);
    cudaGetSymbolAddress((void**)&p_nb_p, g_nb_p);
    cudaGetSymbolAddress((void**)&p_nb_a, g_nb_a);
    cudaGetSymbolAddress((void**)&p_vkq, g_vkq);
    cudaGetSymbolAddress((void**)&p_cnt, g_cnt);
    cudaGetSymbolAddress((void**)&p_off, g_off);
    cudaGetSymbolAddress((void**)&p_cur, g_cur);
    cudaGetSymbolAddress((void**)&p_bsum, g_bsum);
    cudaGetSymbolAddress((void**)&p_edge, g_edge);

    const int EB = (NEDGE + 255) / 256;
    const int NBK = (NNODES + 255) / 256;

    // 1. fold attention projections
    vkq_kernel<<<1, 256>>>(w_keys_p, w_query_p, w_att_p, w_keys_a, w_query_a, w_att_a);

    // 2. CSR build for both relations (rel 0 = adj_a, rel 1 = adj_p)
    zero_cnt_kernel<<<(2 * NNODES + 255) / 256, 256>>>();
    hist_kernel<<<EB, 256>>>(adj_a_row, p_cnt);
    hist_kernel<<<EB, 256>>>(adj_p_row, p_cnt + NNODES);
    for (int rel = 0; rel < 2; rel++) {
        scan1_kernel<<<NB, SCAN_BLK>>>(p_cnt + rel * NNODES, p_off + rel * NNODES,
                                       p_bsum + rel * (NB + 1));
        scan2_kernel<<<1, 32>>>(p_bsum + rel * (NB + 1));
        scan3_kernel<<<NBK, 256>>>(p_off + rel * NNODES, p_cur + rel * NNODES,
                                   p_bsum + rel * (NB + 1));
    }
    scatter_kernel<<<EB, 256>>>(adj_a_row, adj_a_col, adj_a_val, p_cur, p_edge);
    scatter_kernel<<<EB, 256>>>(adj_p_row, adj_p_col, adj_p_val, p_cur + NNODES, p_edge + NEDGE);

    // 3. fused dual GEMMs (f32x2 packed FMA)
    int gblocks = (NNODES + BM - 1) / BM;
    gemm_dual_kernel<<<gblocks, 128>>>(x_p, w_self_p, w_rel_a_p, p_self_p, p_rels_p, NNODES);
    gemm_dual_kernel<<<gblocks, 128>>>(x_a, w_self_a, w_rel_p_a, p_self_a, p_rels_a, NNODES);

    // 4. gather-only SpMM
    int sblocks = (NNODES * 32 + 255) / 256;
    spmm_csr_kernel<<<sblocks, 256>>>(p_off, p_cnt, p_edge, p_rels_a, p_nb_p);
    spmm_csr_kernel<<<sblocks, 256>>>(p_off + NNODES, p_cnt + NNODES, p_edge + NEDGE,
                                      p_rels_p, p_nb_a);

    // 5. attention + output
    int fblocks = (NNODES * 32 + 255) / 256;
    finalize_kernel<<<fblocks, 256>>>(p_self_p, p_nb_p, bias_p, p_vkq + 0 * DOUT, p_vkq + 1 * DOUT,
                                      out_p, att_p);
    finalize_kernel<<<fblocks, 256>>>(p_self_a, p_nb_a, bias_a, p_vkq + 2 * DOUT, p_vkq + 3 * DOUT,
                                      out_a, att_a);
}

// round 3
// speedup vs baseline: 1.3487x; 1.1522x over previous
#include <cuda_runtime.h>
#include <math.h>

#define NNODES 100000
#define DIN 256
#define DOUT 64
#define NEDGE 3200000
#define SCAN_BLK 1024
#define NB ((NNODES + SCAN_BLK - 1) / SCAN_BLK)   // 98

// ---------------- scratch (device globals; no allocation allowed) ----------------
__device__ float g_self_p[NNODES * DOUT];   // x_p @ w_self_p
__device__ float g_rels_p[NNODES * DOUT];   // x_p @ w_rel_a_p
__device__ float g_self_a[NNODES * DOUT];   // x_a @ w_self_a
__device__ float g_rels_a[NNODES * DOUT];   // x_a @ w_rel_p_a
__device__ float g_vkq[4 * DOUT];

// CSR build scratch (2 relations)
__device__ int  g_cnt[2][NNODES];
__device__ int  g_off[2][NNODES];
__device__ int  g_cur[2][NNODES];
__device__ int  g_bsum[2][NB + 1];
__device__ int2 g_edge[2][NEDGE];           // packed {col, val-bits}

// ---------------- fold attention projections into 64-vectors ----------------
__global__ void vkq_kernel(const float* __restrict__ wk_p, const float* __restrict__ wq_p,
                           const float* __restrict__ wa_p,
                           const float* __restrict__ wk_a, const float* __restrict__ wq_a,
                           const float* __restrict__ wa_a) {
    int t = threadIdx.x;
    if (t >= 4 * DOUT) return;
    int which = t >> 6, d = t & 63;
    const float* W; const float* a;
    if (which == 0)      { W = wk_p; a = wa_p; }
    else if (which == 1) { W = wq_p; a = wa_p + DOUT; }
    else if (which == 2) { W = wk_a; a = wa_a; }
    else                 { W = wq_a; a = wa_a + DOUT; }
    float s = 0.f;
#pragma unroll 16
    for (int i = 0; i < DOUT; i++) s += W[d * DOUT + i] * a[i];
    g_vkq[which * DOUT + d] = s;
}

// ---------------- CSR build ----------------
__global__ void zero_cnt_kernel() {
    int i = blockIdx.x * blockDim.x + threadIdx.x;
    if (i < 2 * NNODES) ((int*)g_cnt)[i] = 0;
}

__global__ void hist_kernel(const int* __restrict__ row, int* __restrict__ cnt) {
    int e = blockIdx.x * blockDim.x + threadIdx.x;
    if (e < NEDGE) atomicAdd(cnt + __ldg(row + e), 1);   // no return use -> RED
}

__global__ void scan1_kernel(const int* __restrict__ cnt, int* __restrict__ off,
                             int* __restrict__ bsum) {
    __shared__ int s[SCAN_BLK];
    int t = threadIdx.x;
    int i = blockIdx.x * SCAN_BLK + t;
    int v = (i < NNODES) ? cnt[i] : 0;
    s[t] = v;
    __syncthreads();
#pragma unroll
    for (int o = 1; o < SCAN_BLK; o <<= 1) {
        int x = (t >= o) ? s[t - o] : 0;
        __syncthreads();
        s[t] += x;
        __syncthreads();
    }
    if (i < NNODES) off[i] = s[t] - v;      // exclusive within block
    if (t == SCAN_BLK - 1) bsum[blockIdx.x] = s[t];
}

// parallel exclusive scan over the NB (<=128) block sums
__global__ void scan2_kernel(int* __restrict__ bsum) {
    __shared__ int s[128];
    int t = threadIdx.x;
    int v = (t < NB) ? bsum[t] : 0;
    s[t] = v;
    __syncthreads();
#pragma unroll
    for (int o = 1; o < 128; o <<= 1) {
        int x = (t >= o) ? s[t - o] : 0;
        __syncthreads();
        s[t] += x;
        __syncthreads();
    }
    if (t < NB) bsum[t] = s[t] - v;          // exclusive
}

__global__ void scan3_kernel(int* __restrict__ off, int* __restrict__ cur,
                             const int* __restrict__ bsum) {
    int i = blockIdx.x * blockDim.x + threadIdx.x;
    if (i < NNODES) {
        int o = off[i] + bsum[i >> 10];
        off[i] = o;
        cur[i] = o;
    }
}

__global__ void scatter_kernel(const int* __restrict__ row, const int* __restrict__ col,
                               const float* __restrict__ val, int* __restrict__ cur,
                               int2* __restrict__ edges) {
    int e = blockIdx.x * blockDim.x + threadIdx.x;
    if (e >= NEDGE) return;
    int r = __ldg(row + e);
    int pos = atomicAdd(cur + r, 1);
    edges[pos] = make_int2(__ldg(col + e), __float_as_int(__ldg(val + e)));
}

// ---------------- fused SpMM + attention + output: warp per dst node ----------------
__global__ __launch_bounds__(256) void spmm_final_kernel(
    const int* __restrict__ off, const int* __restrict__ cnt, const int2* __restrict__ edges,
    const float* __restrict__ src,                       // rel-transformed neighbor feats
    const float* __restrict__ selfft, const float* __restrict__ bias,
    const float* __restrict__ vk, const float* __restrict__ vq,
    float* __restrict__ out, float* __restrict__ att)
{
    int gw = (blockIdx.x * blockDim.x + threadIdx.x) >> 5;
    int lane = threadIdx.x & 31;
    if (gw >= NNODES) return;
    int start = __ldg(off + gw);
    int deg   = __ldg(cnt + gw);

    float acc0 = 0.f, acc1 = 0.f;
    int i = 0;
    for (; i + 4 <= deg; i += 4) {                  // 4-deep pipeline for MLP
        int2 e0 = __ldg(edges + start + i);
        int2 e1 = __ldg(edges + start + i + 1);
        int2 e2 = __ldg(edges + start + i + 2);
        int2 e3 = __ldg(edges + start + i + 3);
        const float* s0 = src + (size_t)e0.x * DOUT;
        const float* s1 = src + (size_t)e1.x * DOUT;
        const float* s2 = src + (size_t)e2.x * DOUT;
        const float* s3 = src + (size_t)e3.x * DOUT;
        float x00 = __ldg(s0 + lane), x01 = __ldg(s0 + 32 + lane);
        float x10 = __ldg(s1 + lane), x11 = __ldg(s1 + 32 + lane);
        float x20 = __ldg(s2 + lane), x21 = __ldg(s2 + 32 + lane);
        float x30 = __ldg(s3 + lane), x31 = __ldg(s3 + 32 + lane);
        float v0 = __int_as_float(e0.y), v1 = __int_as_float(e1.y);
        float v2 = __int_as_float(e2.y), v3 = __int_as_float(e3.y);
        acc0 = fmaf(v0, x00, acc0); acc1 = fmaf(v0, x01, acc1);
        acc0 = fmaf(v1, x10, acc0); acc1 = fmaf(v1, x11, acc1);
        acc0 = fmaf(v2, x20, acc0); acc1 = fmaf(v2, x21, acc1);
        acc0 = fmaf(v3, x30, acc0); acc1 = fmaf(v3, x31, acc1);
    }
    for (; i < deg; i++) {
        int2 e0 = __ldg(edges + start + i);
        const float* s0 = src + (size_t)e0.x * DOUT;
        float v0 = __int_as_float(e0.y);
        acc0 = fmaf(v0, __ldg(s0 + lane), acc0);
        acc1 = fmaf(v0, __ldg(s0 + 32 + lane), acc1);
    }

    // ---- attention + output (former finalize) ----
    size_t base = (size_t)gw * DOUT;
    float s0 = selfft[base + lane], s1 = selfft[base + 32 + lane];
    float n0 = acc0, n1 = acc1;
    float vk0 = vk[lane], vk1 = vk[32 + lane];
    float vq0 = vq[lane], vq1 = vq[32 + lane];

    float d_skq = s0 * (vk0 + vq0) + s1 * (vk1 + vq1);
    float d_sq  = s0 * vq0 + s1 * vq1;
    float d_nk  = n0 * vk0 + n1 * vk1;
#pragma unroll
    for (int o = 16; o; o >>= 1) {
        d_skq += __shfl_xor_sync(0xffffffffu, d_skq, o);
        d_sq  += __shfl_xor_sync(0xffffffffu, d_sq,  o);
        d_nk  += __shfl_xor_sync(0xffffffffu, d_nk,  o);
    }
    float e0v = d_skq;
    float e1v = d_nk + d_sq;
    e0v = (e0v > 0.f) ? e0v : expm1f(e0v);   // elu
    e1v = (e1v > 0.f) ? e1v : expm1f(e1v);
    float m = fmaxf(e0v, e1v);
    float a0 = expf(e0v - m), a1 = expf(e1v - m);
    float inv = 1.f / (a0 + a1);
    a0 *= inv; a1 *= inv;

    out[base + lane]      = fmaf(a0, s0, fmaf(a1, n0, bias[lane]));
    out[base + 32 + lane] = fmaf(a0, s1, fmaf(a1, n1, bias[32 + lane]));
    if (lane == 0) { att[(size_t)gw * 2] = a0; att[(size_t)gw * 2 + 1] = a1; }
}

// ---------------- fused dual-weight GEMM with packed f32x2 FMA ----------------
#define BM 64
#define BN 128
#define BK 16

union F2 { float2 f; unsigned long long u; };

__global__ __launch_bounds__(128) void gemm_dual_kernel(
    const float* __restrict__ X, const float* __restrict__ Ws, const float* __restrict__ Wr,
    float* __restrict__ Cs, float* __restrict__ Cr, int nrows)
{
    __shared__ float As[BK][BM];        // transposed tile: As[k][m]
    __shared__ float Bs[BK][BN];

    const int tid = threadIdx.x;        // 0..127
    const int block_row = blockIdx.x * BM;
    const int rg = tid >> 4;            // 0..7  (row group of 8)
    const int cg = tid & 15;            // 0..15 (col group of 8)

    F2 acc[4][8];
#pragma unroll
    for (int i = 0; i < 4; i++)
#pragma unroll
        for (int j = 0; j < 8; j++) acc[i][j].u = 0ULL;

    for (int k0 = 0; k0 < DIN; k0 += BK) {
#pragma unroll
        for (int i = tid; i < BM * BK / 4; i += 128) {
            int m = i >> 2, kq = i & 3;
            int r = block_row + m;
            float4 v = make_float4(0.f, 0.f, 0.f, 0.f);
            if (r < nrows)
                v = *(const float4*)(X + (size_t)r * DIN + k0 + kq * 4);
            As[kq * 4 + 0][m] = v.x;
            As[kq * 4 + 1][m] = v.y;
            As[kq * 4 + 2][m] = v.z;
            As[kq * 4 + 3][m] = v.w;
        }
#pragma unroll
        for (int i = tid; i < BK * BN / 4; i += 128) {
            int k = i >> 5;
            int c4 = i & 31;
            float4 v;
            if (c4 < 16) v = *(const float4*)(Ws + (size_t)(k0 + k) * DOUT + c4 * 4);
            else         v = *(const float4*)(Wr + (size_t)(k0 + k) * DOUT + (c4 - 16) * 4);
            *(float4*)&Bs[k][c4 * 4] = v;
        }
        __syncthreads();

#pragma unroll
        for (int k = 0; k < BK; k++) {
            float4 a0 = *(const float4*)&As[k][rg * 8];
            float4 a1 = *(const float4*)&As[k][rg * 8 + 4];
            float4 b0 = *(const float4*)&Bs[k][cg * 8];
            float4 b1 = *(const float4*)&Bs[k][cg * 8 + 4];

            F2 ap[4];
            ap[0].f = make_float2(a0.x, a0.y);
            ap[1].f = make_float2(a0.z, a0.w);
            ap[2].f = make_float2(a1.x, a1.y);
            ap[3].f = make_float2(a1.z, a1.w);

            float bv[8] = {b0.x, b0.y, b0.z, b0.w, b1.x, b1.y, b1.z, b1.w};
#pragma unroll
            for (int j = 0; j < 8; j++) {
                F2 bd; bd.f = make_float2(bv[j], bv[j]);
#pragma unroll
                for (int ip = 0; ip < 4; ip++) {
                    asm("fma.rn.f32x2 %0, %1, %2, %3;"
                        : "=l"(acc[ip][j].u)
                        : "l"(ap[ip].u), "l"(bd.u), "l"(acc[ip][j].u));
                }
            }
        }
        __syncthreads();
    }

    const int cbase = cg * 8;
    float* Cout = (cbase < 64) ? Cs : Cr;
    const int ccol = (cbase < 64) ? cbase : (cbase - 64);
#pragma unroll
    for (int ip = 0; ip < 4; ip++) {
        int r0 = block_row + rg * 8 + 2 * ip;
        int r1 = r0 + 1;
        if (r0 < nrows) {
            *(float4*)(Cout + (size_t)r0 * DOUT + ccol) =
                make_float4(acc[ip][0].f.x, acc[ip][1].f.x, acc[ip][2].f.x, acc[ip][3].f.x);
            *(float4*)(Cout + (size_t)r0 * DOUT + ccol + 4) =
                make_float4(acc[ip][4].f.x, acc[ip][5].f.x, acc[ip][6].f.x, acc[ip][7].f.x);
        }
        if (r1 < nrows) {
            *(float4*)(Cout + (size_t)r1 * DOUT + ccol) =
                make_float4(acc[ip][0].f.y, acc[ip][1].f.y, acc[ip][2].f.y, acc[ip][3].f.y);
            *(float4*)(Cout + (size_t)r1 * DOUT + ccol + 4) =
                make_float4(acc[ip][4].f.y, acc[ip][5].f.y, acc[ip][6].f.y, acc[ip][7].f.y);
        }
    }
}

// ---------------- launch ----------------
extern "C" void kernel_launch(void* const* d_in, const int* in_sizes, int n_in,
                              void* d_out, int out_size) {
    const float* x_p       = (const float*)d_in[0];
    const float* x_a       = (const float*)d_in[1];
    const int*   adj_a_row = (const int*)d_in[2];
    const int*   adj_a_col = (const int*)d_in[3];
    const float* adj_a_val = (const float*)d_in[4];
    const int*   adj_p_row = (const int*)d_in[5];
    const int*   adj_p_col = (const int*)d_in[6];
    const float* adj_p_val = (const float*)d_in[7];
    const float* w_self_p  = (const float*)d_in[8];
    const float* w_rel_p_a = (const float*)d_in[9];
    const float* bias_p    = (const float*)d_in[10];
    const float* w_query_p = (const float*)d_in[11];
    const float* w_keys_p  = (const float*)d_in[12];
    const float* w_att_p   = (const float*)d_in[13];
    const float* w_self_a  = (const float*)d_in[14];
    const float* w_rel_a_p = (const float*)d_in[15];
    const float* bias_a    = (const float*)d_in[16];
    const float* w_query_a = (const float*)d_in[17];
    const float* w_keys_a  = (const float*)d_in[18];
    const float* w_att_a   = (const float*)d_in[19];

    float* out = (float*)d_out;
    float* out_p = out;
    float* out_a = out + (size_t)NNODES * DOUT;
    float* att_p = out + (size_t)2 * NNODES * DOUT;
    float* att_a = att_p + (size_t)NNODES * 2;

    float *p_self_p, *p_rels_p, *p_self_a, *p_rels_a, *p_vkq;
    int *p_cnt, *p_off, *p_cur, *p_bsum;
    int2 *p_edge;
    cudaGetSymbolAddress((void**)&p_self_p, g_self_p);
    cudaGetSymbolAddress((void**)&p_rels_p, g_rels_p);
    cudaGetSymbolAddress((void**)&p_self_a, g_self_a);
    cudaGetSymbolAddress((void**)&p_rels_a, g_rels_a);
    cudaGetSymbolAddress((void**)&p_vkq, g_vkq);
    cudaGetSymbolAddress((void**)&p_cnt, g_cnt);
    cudaGetSymbolAddress((void**)&p_off, g_off);
    cudaGetSymbolAddress((void**)&p_cur, g_cur);
    cudaGetSymbolAddress((void**)&p_bsum, g_bsum);
    cudaGetSymbolAddress((void**)&p_edge, g_edge);

    // side stream + events (created once, pre-capture on the correctness call;
    // reuse across capture is legal — host objects, not device memory)
    static cudaStream_t s1 = nullptr;
    static cudaEvent_t e_fork = nullptr, e_join = nullptr;
    if (s1 == nullptr) {
        cudaStreamCreateWithFlags(&s1, cudaStreamNonBlocking);
        cudaEventCreateWithFlags(&e_fork, cudaEventDisableTiming);
        cudaEventCreateWithFlags(&e_join, cudaEventDisableTiming);
    }

    const int EB = (NEDGE + 255) / 256;
    const int NBK = (NNODES + 255) / 256;

    // fork: CSR build chain on s1, GEMM chain on the default stream
    cudaEventRecord(e_fork, 0);
    cudaStreamWaitEvent(s1, e_fork, 0);

    // ---- s1: CSR build for both relations (rel 0 = adj_a, rel 1 = adj_p) ----
    zero_cnt_kernel<<<(2 * NNODES + 255) / 256, 256, 0, s1>>>();
    hist_kernel<<<EB, 256, 0, s1>>>(adj_a_row, p_cnt);
    hist_kernel<<<EB, 256, 0, s1>>>(adj_p_row, p_cnt + NNODES);
    for (int rel = 0; rel < 2; rel++) {
        scan1_kernel<<<NB, SCAN_BLK, 0, s1>>>(p_cnt + rel * NNODES, p_off + rel * NNODES,
                                              p_bsum + rel * (NB + 1));
        scan2_kernel<<<1, 128, 0, s1>>>(p_bsum + rel * (NB + 1));
        scan3_kernel<<<NBK, 256, 0, s1>>>(p_off + rel * NNODES, p_cur + rel * NNODES,
                                          p_bsum + rel * (NB + 1));
    }
    scatter_kernel<<<EB, 256, 0, s1>>>(adj_a_row, adj_a_col, adj_a_val, p_cur, p_edge);
    scatter_kernel<<<EB, 256, 0, s1>>>(adj_p_row, adj_p_col, adj_p_val, p_cur + NNODES,
                                       p_edge + NEDGE);
    cudaEventRecord(e_join, s1);

    // ---- default stream: attention fold + dual GEMMs ----
    vkq_kernel<<<1, 256>>>(w_keys_p, w_query_p, w_att_p, w_keys_a, w_query_a, w_att_a);
    int gblocks = (NNODES + BM - 1) / BM;
    gemm_dual_kernel<<<gblocks, 128>>>(x_a, w_self_a, w_rel_p_a, p_self_a, p_rels_a, NNODES);
    gemm_dual_kernel<<<gblocks, 128>>>(x_p, w_self_p, w_rel_a_p, p_self_p, p_rels_p, NNODES);

    // join, then fused SpMM + attention + output
    cudaStreamWaitEvent(0, e_join, 0);
    int sblocks = (NNODES * 32 + 255) / 256;
    // out_p: aggregate adj_a over (x_a @ w_rel_p_a) = g_rels_a
    spmm_final_kernel<<<sblocks, 256>>>(p_off, p_cnt, p_edge, p_rels_a,
                                        p_self_p, bias_p, p_vkq + 0 * DOUT, p_vkq + 1 * DOUT,
                                        out_p, att_p);
    // out_a: aggregate adj_p over (x_p @ w_rel_a_p) = g_rels_p
    spmm_final_kernel<<<sblocks, 256>>>(p_off + NNODES, p_cnt + NNODES, p_edge + NEDGE, p_rels_p,
                                        p_self_a, bias_a, p_vkq + 2 * DOUT, p_vkq + 3 * DOUT,
                                        out_a, att_a);
}

// round 4
// speedup vs baseline: 1.4350x; 1.0640x over previous
#include <cuda_runtime.h>
#include <cuda_fp16.h>
#include <math.h>

#define NNODES 100000
#define DIN 256
#define DOUT 64
#define NEDGE 3200000
#define SCAN_BLK 1024
#define NB ((NNODES + SCAN_BLK - 1) / SCAN_BLK)   // 98

// ---------------- scratch (device globals; no allocation allowed) ----------------
__device__ float   g_self_p[NNODES * DOUT];    // x_p @ w_self_p          (fp32, exact)
__device__ float   g_self_a[NNODES * DOUT];    // x_a @ w_self_a
__device__ __half2 g_rels_p[NNODES * DOUT/2];  // x_p @ w_rel_a_p  (fp16, gather table)
__device__ __half2 g_rels_a[NNODES * DOUT/2];  // x_a @ w_rel_p_a
__device__ float   g_nb_p[NNODES * DOUT];      // aggregated neighbor feats (interleaved)
__device__ float   g_nb_a[NNODES * DOUT];
__device__ float   g_vkq[4 * DOUT];

// CSR build scratch (2 relations)
__device__ int  g_cnt[2][NNODES];
__device__ int  g_off[2][NNODES];
__device__ int  g_cur[2][NNODES];
__device__ int  g_bsum[2][NB + 1];
__device__ int2 g_edge[2][NEDGE];              // packed {col, val-bits}

// ---------------- fold attention projections into 64-vectors ----------------
__global__ void vkq_kernel(const float* __restrict__ wk_p, const float* __restrict__ wq_p,
                           const float* __restrict__ wa_p,
                           const float* __restrict__ wk_a, const float* __restrict__ wq_a,
                           const float* __restrict__ wa_a) {
    int t = threadIdx.x;
    if (t >= 4 * DOUT) return;
    int which = t >> 6, d = t & 63;
    const float* W; const float* a;
    if (which == 0)      { W = wk_p; a = wa_p; }
    else if (which == 1) { W = wq_p; a = wa_p + DOUT; }
    else if (which == 2) { W = wk_a; a = wa_a; }
    else                 { W = wq_a; a = wa_a + DOUT; }
    float s = 0.f;
#pragma unroll 16
    for (int i = 0; i < DOUT; i++) s += W[d * DOUT + i] * a[i];
    g_vkq[which * DOUT + d] = s;
}

// ---------------- CSR build ----------------
__global__ void zero_cnt_kernel() {
    int i = blockIdx.x * blockDim.x + threadIdx.x;
    if (i < 2 * NNODES) ((int*)g_cnt)[i] = 0;
}

__global__ void hist_kernel(const int* __restrict__ row, int* __restrict__ cnt) {
    int e = blockIdx.x * blockDim.x + threadIdx.x;
    if (e < NEDGE) atomicAdd(cnt + __ldg(row + e), 1);   // no return use -> RED
}

__global__ void scan1_kernel(const int* __restrict__ cnt, int* __restrict__ off,
                             int* __restrict__ bsum) {
    __shared__ int s[SCAN_BLK];
    int t = threadIdx.x;
    int i = blockIdx.x * SCAN_BLK + t;
    int v = (i < NNODES) ? cnt[i] : 0;
    s[t] = v;
    __syncthreads();
#pragma unroll
    for (int o = 1; o < SCAN_BLK; o <<= 1) {
        int x = (t >= o) ? s[t - o] : 0;
        __syncthreads();
        s[t] += x;
        __syncthreads();
    }
    if (i < NNODES) off[i] = s[t] - v;      // exclusive within block
    if (t == SCAN_BLK - 1) bsum[blockIdx.x] = s[t];
}

__global__ void scan2_kernel(int* __restrict__ bsum) {
    __shared__ int s[128];
    int t = threadIdx.x;
    int v = (t < NB) ? bsum[t] : 0;
    s[t] = v;
    __syncthreads();
#pragma unroll
    for (int o = 1; o < 128; o <<= 1) {
        int x = (t >= o) ? s[t - o] : 0;
        __syncthreads();
        s[t] += x;
        __syncthreads();
    }
    if (t < NB) bsum[t] = s[t] - v;          // exclusive
}

__global__ void scan3_kernel(int* __restrict__ off, int* __restrict__ cur,
                             const int* __restrict__ bsum) {
    int i = blockIdx.x * blockDim.x + threadIdx.x;
    if (i < NNODES) {
        int o = off[i] + bsum[i >> 10];
        off[i] = o;
        cur[i] = o;
    }
}

__global__ void scatter_kernel(const int* __restrict__ row, const int* __restrict__ col,
                               const float* __restrict__ val, int* __restrict__ cur,
                               int2* __restrict__ edges) {
    int e = blockIdx.x * blockDim.x + threadIdx.x;
    if (e >= NEDGE) return;
    int r = __ldg(row + e);
    int pos = atomicAdd(cur + r, 1);
    edges[pos] = make_int2(__ldg(col + e), __float_as_int(__ldg(val + e)));
}

// ---------------- gather SpMM: warp per dst node, fp16 source rows ----------------
// output layout: nb[node*64 + 2*lane], nb[node*64 + 2*lane + 1]  (interleaved)
__global__ __launch_bounds__(256) void spmm_nb_kernel(
    const int* __restrict__ off, const int* __restrict__ cnt, const int2* __restrict__ edges,
    const __half2* __restrict__ src, float* __restrict__ nb)
{
    int gw = (blockIdx.x * blockDim.x + threadIdx.x) >> 5;
    int lane = threadIdx.x & 31;
    if (gw >= NNODES) return;
    int start = __ldg(off + gw);
    int deg   = __ldg(cnt + gw);

    float a0 = 0.f, a1 = 0.f;
    int i = 0;
    for (; i + 4 <= deg; i += 4) {
        int2 e0 = __ldg(edges + start + i);
        int2 e1 = __ldg(edges + start + i + 1);
        int2 e2 = __ldg(edges + start + i + 2);
        int2 e3 = __ldg(edges + start + i + 3);
        __half2 h0 = __ldg(src + (size_t)e0.x * 32 + lane);
        __half2 h1 = __ldg(src + (size_t)e1.x * 32 + lane);
        __half2 h2 = __ldg(src + (size_t)e2.x * 32 + lane);
        __half2 h3 = __ldg(src + (size_t)e3.x * 32 + lane);
        float v0 = __int_as_float(e0.y), v1 = __int_as_float(e1.y);
        float v2 = __int_as_float(e2.y), v3 = __int_as_float(e3.y);
        float2 f0 = __half22float2(h0), f1 = __half22float2(h1);
        float2 f2 = __half22float2(h2), f3 = __half22float2(h3);
        a0 = fmaf(v0, f0.x, a0); a1 = fmaf(v0, f0.y, a1);
        a0 = fmaf(v1, f1.x, a0); a1 = fmaf(v1, f1.y, a1);
        a0 = fmaf(v2, f2.x, a0); a1 = fmaf(v2, f2.y, a1);
        a0 = fmaf(v3, f3.x, a0); a1 = fmaf(v3, f3.y, a1);
    }
    for (; i < deg; i++) {
        int2 e0 = __ldg(edges + start + i);
        __half2 h0 = __ldg(src + (size_t)e0.x * 32 + lane);
        float v0 = __int_as_float(e0.y);
        float2 f0 = __half22float2(h0);
        a0 = fmaf(v0, f0.x, a0); a1 = fmaf(v0, f0.y, a1);
    }
    *(float2*)(nb + (size_t)gw * DOUT + 2 * lane) = make_float2(a0, a1);
}

// ---------------- attention mix + output, warp per node (interleaved layout) --------
__global__ __launch_bounds__(256) void finalize_kernel(
    const float* __restrict__ selfft, const float* __restrict__ nbft,
    const float* __restrict__ bias, const float* __restrict__ vk, const float* __restrict__ vq,
    float* __restrict__ out, float* __restrict__ att)
{
    int gw = (blockIdx.x * blockDim.x + threadIdx.x) >> 5;
    int lane = threadIdx.x & 31;
    if (gw >= NNODES) return;
    size_t base = (size_t)gw * DOUT;

    float2 s = *(const float2*)(selfft + base + 2 * lane);
    float2 n = *(const float2*)(nbft + base + 2 * lane);
    float2 k = *(const float2*)(vk + 2 * lane);
    float2 q = *(const float2*)(vq + 2 * lane);
    float2 b = *(const float2*)(bias + 2 * lane);

    float d_skq = s.x * (k.x + q.x) + s.y * (k.y + q.y);
    float d_sq  = s.x * q.x + s.y * q.y;
    float d_nk  = n.x * k.x + n.y * k.y;
#pragma unroll
    for (int o = 16; o; o >>= 1) {
        d_skq += __shfl_xor_sync(0xffffffffu, d_skq, o);
        d_sq  += __shfl_xor_sync(0xffffffffu, d_sq,  o);
        d_nk  += __shfl_xor_sync(0xffffffffu, d_nk,  o);
    }
    float e0v = d_skq;
    float e1v = d_nk + d_sq;
    e0v = (e0v > 0.f) ? e0v : expm1f(e0v);   // elu
    e1v = (e1v > 0.f) ? e1v : expm1f(e1v);
    float m = fmaxf(e0v, e1v);
    float a0 = expf(e0v - m), a1 = expf(e1v - m);
    float inv = 1.f / (a0 + a1);
    a0 *= inv; a1 *= inv;

    float2 o2 = make_float2(fmaf(a0, s.x, fmaf(a1, n.x, b.x)),
                            fmaf(a0, s.y, fmaf(a1, n.y, b.y)));
    *(float2*)(out + base + 2 * lane) = o2;
    if (lane == 0) { att[(size_t)gw * 2] = a0; att[(size_t)gw * 2 + 1] = a1; }
}

// ---------------- fused dual-weight GEMM with packed f32x2 FMA ----------------
// Cs (self path) stored fp32; Cr (rel path) stored fp16 for the SpMM gather.
#define BM 64
#define BN 128
#define BK 16

union F2 { float2 f; unsigned long long u; };
union H8 { __half2 h[4]; uint4 u; };

__global__ __launch_bounds__(128) void gemm_dual_kernel(
    const float* __restrict__ X, const float* __restrict__ Ws, const float* __restrict__ Wr,
    float* __restrict__ Cs, __half* __restrict__ Cr, int nrows)
{
    __shared__ float As[BK][BM];        // transposed tile: As[k][m]
    __shared__ float Bs[BK][BN];

    const int tid = threadIdx.x;        // 0..127
    const int block_row = blockIdx.x * BM;
    const int rg = tid >> 4;            // 0..7  (row group of 8)
    const int cg = tid & 15;            // 0..15 (col group of 8)

    F2 acc[4][8];
#pragma unroll
    for (int i = 0; i < 4; i++)
#pragma unroll
        for (int j = 0; j < 8; j++) acc[i][j].u = 0ULL;

    for (int k0 = 0; k0 < DIN; k0 += BK) {
#pragma unroll
        for (int i = tid; i < BM * BK / 4; i += 128) {
            int m = i >> 2, kq = i & 3;
            int r = block_row + m;
            float4 v = make_float4(0.f, 0.f, 0.f, 0.f);
            if (r < nrows)
                v = *(const float4*)(X + (size_t)r * DIN + k0 + kq * 4);
            As[kq * 4 + 0][m] = v.x;
            As[kq * 4 + 1][m] = v.y;
            As[kq * 4 + 2][m] = v.z;
            As[kq * 4 + 3][m] = v.w;
        }
#pragma unroll
        for (int i = tid; i < BK * BN / 4; i += 128) {
            int k = i >> 5;
            int c4 = i & 31;
            float4 v;
            if (c4 < 16) v = *(const float4*)(Ws + (size_t)(k0 + k) * DOUT + c4 * 4);
            else         v = *(const float4*)(Wr + (size_t)(k0 + k) * DOUT + (c4 - 16) * 4);
            *(float4*)&Bs[k][c4 * 4] = v;
        }
        __syncthreads();

#pragma unroll
        for (int k = 0; k < BK; k++) {
            float4 a0 = *(const float4*)&As[k][rg * 8];
            float4 a1 = *(const float4*)&As[k][rg * 8 + 4];
            float4 b0 = *(const float4*)&Bs[k][cg * 8];
            float4 b1 = *(const float4*)&Bs[k][cg * 8 + 4];

            F2 ap[4];
            ap[0].f = make_float2(a0.x, a0.y);
            ap[1].f = make_float2(a0.z, a0.w);
            ap[2].f = make_float2(a1.x, a1.y);
            ap[3].f = make_float2(a1.z, a1.w);

            float bv[8] = {b0.x, b0.y, b0.z, b0.w, b1.x, b1.y, b1.z, b1.w};
#pragma unroll
            for (int j = 0; j < 8; j++) {
                F2 bd; bd.f = make_float2(bv[j], bv[j]);
#pragma unroll
                for (int ip = 0; ip < 4; ip++) {
                    asm("fma.rn.f32x2 %0, %1, %2, %3;"
                        : "=l"(acc[ip][j].u)
                        : "l"(ap[ip].u), "l"(bd.u), "l"(acc[ip][j].u));
                }
            }
        }
        __syncthreads();
    }

    const int cbase = cg * 8;
    if (cbase < 64) {
        // self path: fp32
        const int ccol = cbase;
#pragma unroll
        for (int ip = 0; ip < 4; ip++) {
            int r0 = block_row + rg * 8 + 2 * ip;
            int r1 = r0 + 1;
            if (r0 < nrows) {
                *(float4*)(Cs + (size_t)r0 * DOUT + ccol) =
                    make_float4(acc[ip][0].f.x, acc[ip][1].f.x, acc[ip][2].f.x, acc[ip][3].f.x);
                *(float4*)(Cs + (size_t)r0 * DOUT + ccol + 4) =
                    make_float4(acc[ip][4].f.x, acc[ip][5].f.x, acc[ip][6].f.x, acc[ip][7].f.x);
            }
            if (r1 < nrows) {
                *(float4*)(Cs + (size_t)r1 * DOUT + ccol) =
                    make_float4(acc[ip][0].f.y, acc[ip][1].f.y, acc[ip][2].f.y, acc[ip][3].f.y);
                *(float4*)(Cs + (size_t)r1 * DOUT + ccol + 4) =
                    make_float4(acc[ip][4].f.y, acc[ip][5].f.y, acc[ip][6].f.y, acc[ip][7].f.y);
            }
        }
    } else {
        // rel path: fp16 (8 halves = 16 B per row-strip store)
        const int ccol = cbase - 64;
#pragma unroll
        for (int ip = 0; ip < 4; ip++) {
            int r0 = block_row + rg * 8 + 2 * ip;
            int r1 = r0 + 1;
            if (r0 < nrows) {
                H8 p;
                p.h[0] = __floats2half2_rn(acc[ip][0].f.x, acc[ip][1].f.x);
                p.h[1] = __floats2half2_rn(acc[ip][2].f.x, acc[ip][3].f.x);
                p.h[2] = __floats2half2_rn(acc[ip][4].f.x, acc[ip][5].f.x);
                p.h[3] = __floats2half2_rn(acc[ip][6].f.x, acc[ip][7].f.x);
                *(uint4*)(Cr + (size_t)r0 * DOUT + ccol) = p.u;
            }
            if (r1 < nrows) {
                H8 p;
                p.h[0] = __floats2half2_rn(acc[ip][0].f.y, acc[ip][1].f.y);
                p.h[1] = __floats2half2_rn(acc[ip][2].f.y, acc[ip][3].f.y);
                p.h[2] = __floats2half2_rn(acc[ip][4].f.y, acc[ip][5].f.y);
                p.h[3] = __floats2half2_rn(acc[ip][6].f.y, acc[ip][7].f.y);
                *(uint4*)(Cr + (size_t)r1 * DOUT + ccol) = p.u;
            }
        }
    }
}

// ---------------- launch ----------------
extern "C" void kernel_launch(void* const* d_in, const int* in_sizes, int n_in,
                              void* d_out, int out_size) {
    const float* x_p       = (const float*)d_in[0];
    const float* x_a       = (const float*)d_in[1];
    const int*   adj_a_row = (const int*)d_in[2];
    const int*   adj_a_col = (const int*)d_in[3];
    const float* adj_a_val = (const float*)d_in[4];
    const int*   adj_p_row = (const int*)d_in[5];
    const int*   adj_p_col = (const int*)d_in[6];
    const float* adj_p_val = (const float*)d_in[7];
    const float* w_self_p  = (const float*)d_in[8];
    const float* w_rel_p_a = (const float*)d_in[9];
    const float* bias_p    = (const float*)d_in[10];
    const float* w_query_p = (const float*)d_in[11];
    const float* w_keys_p  = (const float*)d_in[12];
    const float* w_att_p   = (const float*)d_in[13];
    const float* w_self_a  = (const float*)d_in[14];
    const float* w_rel_a_p = (const float*)d_in[15];
    const float* bias_a    = (const float*)d_in[16];
    const float* w_query_a = (const float*)d_in[17];
    const float* w_keys_a  = (const float*)d_in[18];
    const float* w_att_a   = (const float*)d_in[19];

    float* out = (float*)d_out;
    float* out_p = out;
    float* out_a = out + (size_t)NNODES * DOUT;
    float* att_p = out + (size_t)2 * NNODES * DOUT;
    float* att_a = att_p + (size_t)NNODES * 2;

    float *p_self_p, *p_self_a, *p_nb_p, *p_nb_a, *p_vkq;
    __half2 *p_rels_p, *p_rels_a;
    int *p_cnt, *p_off, *p_cur, *p_bsum;
    int2 *p_edge;
    cudaGetSymbolAddress((void**)&p_self_p, g_self_p);
    cudaGetSymbolAddress((void**)&p_self_a, g_self_a);
    cudaGetSymbolAddress((void**)&p_rels_p, g_rels_p);
    cudaGetSymbolAddress((void**)&p_rels_a, g_rels_a);
    cudaGetSymbolAddress((void**)&p_nb_p, g_nb_p);
    cudaGetSymbolAddress((void**)&p_nb_a, g_nb_a);
    cudaGetSymbolAddress((void**)&p_vkq, g_vkq);
    cudaGetSymbolAddress((void**)&p_cnt, g_cnt);
    cudaGetSymbolAddress((void**)&p_off, g_off);
    cudaGetSymbolAddress((void**)&p_cur, g_cur);
    cudaGetSymbolAddress((void**)&p_bsum, g_bsum);
    cudaGetSymbolAddress((void**)&p_edge, g_edge);

    static cudaStream_t s1 = nullptr;
    static cudaEvent_t e_fork = nullptr, e_build = nullptr, e_ga = nullptr,
                       e_gp = nullptr, e_sp = nullptr;
    if (s1 == nullptr) {
        cudaStreamCreateWithFlags(&s1, cudaStreamNonBlocking);
        cudaEventCreateWithFlags(&e_fork, cudaEventDisableTiming);
        cudaEventCreateWithFlags(&e_build, cudaEventDisableTiming);
        cudaEventCreateWithFlags(&e_ga, cudaEventDisableTiming);
        cudaEventCreateWithFlags(&e_gp, cudaEventDisableTiming);
        cudaEventCreateWithFlags(&e_sp, cudaEventDisableTiming);
    }

    const int EB = (NEDGE + 255) / 256;
    const int NBK = (NNODES + 255) / 256;
    const int gblocks = (NNODES + BM - 1) / BM;
    const int wblocks = (NNODES * 32 + 255) / 256;   // warp-per-node kernels

    // fork
    cudaEventRecord(e_fork, 0);
    cudaStreamWaitEvent(s1, e_fork, 0);

    // ---- s1: CSR build for both relations (rel 0 = adj_a, rel 1 = adj_p) ----
    zero_cnt_kernel<<<(2 * NNODES + 255) / 256, 256, 0, s1>>>();
    hist_kernel<<<EB, 256, 0, s1>>>(adj_a_row, p_cnt);
    hist_kernel<<<EB, 256, 0, s1>>>(adj_p_row, p_cnt + NNODES);
    for (int rel = 0; rel < 2; rel++) {
        scan1_kernel<<<NB, SCAN_BLK, 0, s1>>>(p_cnt + rel * NNODES, p_off + rel * NNODES,
                                              p_bsum + rel * (NB + 1));
        scan2_kernel<<<1, 128, 0, s1>>>(p_bsum + rel * (NB + 1));
        scan3_kernel<<<NBK, 256, 0, s1>>>(p_off + rel * NNODES, p_cur + rel * NNODES,
                                          p_bsum + rel * (NB + 1));
    }
    scatter_kernel<<<EB, 256, 0, s1>>>(adj_a_row, adj_a_col, adj_a_val, p_cur, p_edge);
    scatter_kernel<<<EB, 256, 0, s1>>>(adj_p_row, adj_p_col, adj_p_val, p_cur + NNODES,
                                       p_edge + NEDGE);
    cudaEventRecord(e_build, s1);

    // ---- s0: attention fold + GEMM_a (produces self_a, rels_a) ----
    vkq_kernel<<<1, 256>>>(w_keys_p, w_query_p, w_att_p, w_keys_a, w_query_a, w_att_a);
    gemm_dual_kernel<<<gblocks, 128>>>(x_a, w_self_a, w_rel_p_a, p_self_a, (__half*)p_rels_a,
                                       NNODES);
    cudaEventRecord(e_ga, 0);

    // ---- s0: GEMM_p (produces self_p, rels_p) ----
    gemm_dual_kernel<<<gblocks, 128>>>(x_p, w_self_p, w_rel_a_p, p_self_p, (__half*)p_rels_p,
                                       NNODES);
    cudaEventRecord(e_gp, 0);

    // ---- s1: spmm_p (needs build + rels_a) — overlaps GEMM_p on s0 ----
    cudaStreamWaitEvent(s1, e_ga, 0);
    spmm_nb_kernel<<<wblocks, 256, 0, s1>>>(p_off, p_cnt, p_edge, p_rels_a, p_nb_p);
    // finalize_p needs self_p (GEMM_p)
    cudaStreamWaitEvent(s1, e_gp, 0);
    finalize_kernel<<<wblocks, 256, 0, s1>>>(p_self_p, p_nb_p, bias_p,
                                             p_vkq + 0 * DOUT, p_vkq + 1 * DOUT, out_p, att_p);
    cudaEventRecord(e_sp, s1);

    // ---- s0: spmm_a (needs build + rels_p) + finalize_a ----
    cudaStreamWaitEvent(0, e_build, 0);
    spmm_nb_kernel<<<wblocks, 256>>>(p_off + NNODES, p_cnt + NNODES, p_edge + NEDGE,
                                     p_rels_p, p_nb_a);
    finalize_kernel<<<wblocks, 256>>>(p_self_a, p_nb_a, bias_a,
                                      p_vkq + 2 * DOUT, p_vkq + 3 * DOUT, out_a, att_a);

    // join s1 back into origin stream
    cudaStreamWaitEvent(0, e_sp, 0);
}